// round 8
// baseline (speedup 1.0000x reference)
#include <cuda_runtime.h>

// RoiPoolingConv: bilinear 7x7 ROI pooling over NHWC feat (1,200,200,512) fp32.
// out shape (1, 300, 7, 7, 512) fp32.
//
// d_in[0]: feat  float32  [1,200,200,512]
// d_in[1]: rois  int32    [1,300,4]  (x0, y0, w, h)
//
// R8: persistent grid-stride kernel with the full ROI table staged in shared
//     memory (4.8 KB, loaded once per CTA). Removes the per-iteration ROI LDG
//     (an L2 round-trip) from the serial dependency chain: each cell now goes
//     LDS(29cyc, broadcast) -> address math -> 4x LDG.128. Per-thread body
//     otherwise identical to the 15.07us R4/R7 code (~32 regs, occ ~80%).

#define POOL 7
#define NUM_ROIS 300
#define FH 200
#define FW 200
#define FC 512
#define TOTAL_CELLS (NUM_ROIS * POOL * POOL)   // 14700
#define NBLOCKS (148 * 16)                     // 2368 persistent CTAs, ~6 iters

__global__ __launch_bounds__(128, 8)
void roi_pool_kernel(const float* __restrict__ feat,
                     const int* __restrict__ rois,
                     float* __restrict__ out) {
    __shared__ int4 s_rois[NUM_ROIS];

    const int c4 = threadIdx.x;   // channel quad 0..127

    // Stage the ROI table once (broadcast-friendly: tiny, L2-hot).
    for (int i = threadIdx.x; i < NUM_ROIS; i += 128)
        s_rois[i] = __ldg(((const int4*)rois) + i);
    __syncthreads();

    for (int idx = blockIdx.x; idx < TOTAL_CELLS; idx += NBLOCKS) {
        const int roi  = idx / (POOL * POOL);
        const int cell = idx - roi * (POOL * POOL);
        const int py = cell / POOL;
        const int px = cell - py * POOL;

        // ROI params from smem: 29-cycle broadcast instead of an L2 round-trip.
        const int4 r = s_rois[roi];
        const int x0 = r.x, y0 = r.y, w = r.z, h = r.w;

        // Match reference math exactly:
        //   sy = py * (h/7), y_lo = floor(sy), y_hi = min(y_lo+1, h-1), fy = sy - y_lo
        const float sy = (float)py * ((float)h / (float)POOL);
        const float sx = (float)px * ((float)w / (float)POOL);
        const int y_lo = (int)floorf(sy);
        const int x_lo = (int)floorf(sx);
        const int y_hi = min(y_lo + 1, h - 1);
        const int x_hi = min(x_lo + 1, w - 1);
        const float fy = sy - (float)y_lo;
        const float fx = sx - (float)x_lo;

        const int ay_lo = y0 + y_lo, ay_hi = y0 + y_hi;
        const int ax_lo = x0 + x_lo, ax_hi = x0 + x_hi;

        // Channel-contiguous NHWC: feat[(y*FW + x)*FC + c]
        const float4* p00 = (const float4*)(feat + ((size_t)ay_lo * FW + ax_lo) * FC);
        const float4* p01 = (const float4*)(feat + ((size_t)ay_lo * FW + ax_hi) * FC);
        const float4* p10 = (const float4*)(feat + ((size_t)ay_hi * FW + ax_lo) * FC);
        const float4* p11 = (const float4*)(feat + ((size_t)ay_hi * FW + ax_hi) * FC);

        // 4 independent 16B loads in flight per thread.
        const float4 v00 = __ldg(p00 + c4);
        const float4 v01 = __ldg(p01 + c4);
        const float4 v10 = __ldg(p10 + c4);
        const float4 v11 = __ldg(p11 + c4);

        const float gx = 1.0f - fx;
        const float gy = 1.0f - fy;

        float4 o;
        {
            float top, bot;
            top = v00.x * gx + v01.x * fx;
            bot = v10.x * gx + v11.x * fx;
            o.x = top * gy + bot * fy;
            top = v00.y * gx + v01.y * fx;
            bot = v10.y * gx + v11.y * fx;
            o.y = top * gy + bot * fy;
            top = v00.z * gx + v01.z * fx;
            bot = v10.z * gx + v11.z * fx;
            o.z = top * gy + bot * fy;
            top = v00.w * gx + v01.w * fx;
            bot = v10.w * gx + v11.w * fx;
            o.w = top * gy + bot * fy;
        }

        // Streaming store: evict-first in L2, keep feat resident.
        float4* outp = (float4*)(out + (size_t)idx * FC);
        __stcs(outp + c4, o);
    }
}

extern "C" void kernel_launch(void* const* d_in, const int* in_sizes, int n_in,
                              void* d_out, int out_size) {
    const float* feat = (const float*)d_in[0];
    const int*   rois = (const int*)d_in[1];
    float*       out  = (float*)d_out;

    roi_pool_kernel<<<NBLOCKS, 128>>>(feat, rois, out);
}

// round 9
// speedup vs baseline: 1.0172x; 1.0172x over previous
#include <cuda_runtime.h>

// RoiPoolingConv: bilinear 7x7 ROI pooling over NHWC feat (1,200,200,512) fp32.
// out shape (1, 300, 7, 7, 512) fp32.
//
// d_in[0]: feat  float32  [1,200,200,512]
// d_in[1]: rois  int32    [1,300,4]  (x0, y0, w, h)
//
// R9: 4 row-consecutive cells per 512-thread CTA. Adjacent cells of the same
//     ROI row share corner columns when w is small; those duplicate pixel
//     reads become same-SM L1 hits instead of L2 round-trips (the only
//     remaining traffic cut). Per-thread body identical to the proven
//     15.07us kernel (~30 regs); 4 CTAs x 16 warps = 64 warps/SM.

#define POOL 7
#define NUM_ROIS 300
#define FH 200
#define FW 200
#define FC 512
#define CELLS (POOL * POOL)      // 49
#define GROUPS 13                // ceil(49/4)

__global__ __launch_bounds__(512, 4)
void roi_pool_kernel(const float* __restrict__ feat,
                     const int* __restrict__ rois,
                     float* __restrict__ out) {
    const int group = blockIdx.x;          // 0..12
    const int roi   = blockIdx.y;          // 0..299
    const int sub   = threadIdx.x >> 7;    // 0..3: which cell of the group
    const int c4    = threadIdx.x & 127;   // channel quad 0..127

    int cell = group * 4 + sub;            // consecutive cells: same row mostly
    const bool valid = (cell < CELLS);
    if (!valid) cell = 0;                  // dup geometry; store suppressed

    const int4 r = __ldg(((const int4*)rois) + roi);
    const int x0 = r.x, y0 = r.y, w = r.z, h = r.w;

    const int py = cell / POOL;
    const int px = cell - py * POOL;

    // Match reference math exactly:
    //   sy = py * (h/7), y_lo = floor(sy), y_hi = min(y_lo+1, h-1), fy = sy - y_lo
    const float sy = (float)py * ((float)h / (float)POOL);
    const float sx = (float)px * ((float)w / (float)POOL);
    const int y_lo = (int)floorf(sy);
    const int x_lo = (int)floorf(sx);
    const int y_hi = min(y_lo + 1, h - 1);
    const int x_hi = min(x_lo + 1, w - 1);
    const float fy = sy - (float)y_lo;
    const float fx = sx - (float)x_lo;

    const int ay_lo = y0 + y_lo, ay_hi = y0 + y_hi;
    const int ax_lo = x0 + x_lo, ax_hi = x0 + x_hi;

    // Channel-contiguous NHWC: feat[(y*FW + x)*FC + c]
    const float4* p00 = (const float4*)(feat + ((size_t)ay_lo * FW + ax_lo) * FC);
    const float4* p01 = (const float4*)(feat + ((size_t)ay_lo * FW + ax_hi) * FC);
    const float4* p10 = (const float4*)(feat + ((size_t)ay_hi * FW + ax_lo) * FC);
    const float4* p11 = (const float4*)(feat + ((size_t)ay_hi * FW + ax_hi) * FC);

    // 4 independent 16B loads in flight per thread.
    const float4 v00 = __ldg(p00 + c4);
    const float4 v01 = __ldg(p01 + c4);
    const float4 v10 = __ldg(p10 + c4);
    const float4 v11 = __ldg(p11 + c4);

    const float gx = 1.0f - fx;
    const float gy = 1.0f - fy;

    float4 o;
    {
        float top, bot;
        top = v00.x * gx + v01.x * fx;
        bot = v10.x * gx + v11.x * fx;
        o.x = top * gy + bot * fy;
        top = v00.y * gx + v01.y * fx;
        bot = v10.y * gx + v11.y * fx;
        o.y = top * gy + bot * fy;
        top = v00.z * gx + v01.z * fx;
        bot = v10.z * gx + v11.z * fx;
        o.z = top * gy + bot * fy;
        top = v00.w * gx + v01.w * fx;
        bot = v10.w * gx + v11.w * fx;
        o.w = top * gy + bot * fy;
    }

    if (valid) {
        // Streaming store: evict-first in L2, keep feat resident.
        float4* outp = (float4*)(out + (((size_t)roi * CELLS) + cell) * FC);
        __stcs(outp + c4, o);
    }
}

extern "C" void kernel_launch(void* const* d_in, const int* in_sizes, int n_in,
                              void* d_out, int out_size) {
    const float* feat = (const float*)d_in[0];
    const int*   rois = (const int*)d_in[1];
    float*       out  = (float*)d_out;

    dim3 grid(GROUPS, NUM_ROIS);   // 4 row-consecutive cells per CTA
    roi_pool_kernel<<<grid, 512>>>(feat, rois, out);
}

// round 10
// speedup vs baseline: 1.0216x; 1.0043x over previous
#include <cuda_runtime.h>

// RoiPoolingConv: bilinear 7x7 ROI pooling over NHWC feat (1,200,200,512) fp32.
// out shape (1, 300, 7, 7, 512) fp32.
//
// d_in[0]: feat  float32  [1,200,200,512]
// d_in[1]: rois  int32    [1,300,4]  (x0, y0, w, h)
//
// R10: R9 (4 row-consecutive cells per 512-thread CTA, 14.85us) + warp-uniform
//      early exit for the 3 invalid padding slots per ROI. R9 duplicated cell 0
//      geometry for those slots and still issued their 4 corner loads
//      (~4.6% of total L2 traffic, pure waste). Exit is per-128-thread
//      sub-block => zero divergence.

#define POOL 7
#define NUM_ROIS 300
#define FH 200
#define FW 200
#define FC 512
#define CELLS (POOL * POOL)      // 49
#define GROUPS 13                // ceil(49/4)

__global__ __launch_bounds__(512, 4)
void roi_pool_kernel(const float* __restrict__ feat,
                     const int* __restrict__ rois,
                     float* __restrict__ out) {
    const int group = blockIdx.x;          // 0..12
    const int roi   = blockIdx.y;          // 0..299
    const int sub   = threadIdx.x >> 7;    // 0..3: which cell of the group
    const int c4    = threadIdx.x & 127;   // channel quad 0..127

    const int cell = group * 4 + sub;      // consecutive cells: same row mostly
    if (cell >= CELLS) return;             // warp-uniform (whole 4-warp sub-block)

    const int4 r = __ldg(((const int4*)rois) + roi);
    const int x0 = r.x, y0 = r.y, w = r.z, h = r.w;

    const int py = cell / POOL;
    const int px = cell - py * POOL;

    // Match reference math exactly:
    //   sy = py * (h/7), y_lo = floor(sy), y_hi = min(y_lo+1, h-1), fy = sy - y_lo
    const float sy = (float)py * ((float)h / (float)POOL);
    const float sx = (float)px * ((float)w / (float)POOL);
    const int y_lo = (int)floorf(sy);
    const int x_lo = (int)floorf(sx);
    const int y_hi = min(y_lo + 1, h - 1);
    const int x_hi = min(x_lo + 1, w - 1);
    const float fy = sy - (float)y_lo;
    const float fx = sx - (float)x_lo;

    const int ay_lo = y0 + y_lo, ay_hi = y0 + y_hi;
    const int ax_lo = x0 + x_lo, ax_hi = x0 + x_hi;

    // Channel-contiguous NHWC: feat[(y*FW + x)*FC + c]
    const float4* p00 = (const float4*)(feat + ((size_t)ay_lo * FW + ax_lo) * FC);
    const float4* p01 = (const float4*)(feat + ((size_t)ay_lo * FW + ax_hi) * FC);
    const float4* p10 = (const float4*)(feat + ((size_t)ay_hi * FW + ax_lo) * FC);
    const float4* p11 = (const float4*)(feat + ((size_t)ay_hi * FW + ax_hi) * FC);

    // 4 independent 16B loads in flight per thread.
    const float4 v00 = __ldg(p00 + c4);
    const float4 v01 = __ldg(p01 + c4);
    const float4 v10 = __ldg(p10 + c4);
    const float4 v11 = __ldg(p11 + c4);

    const float gx = 1.0f - fx;
    const float gy = 1.0f - fy;

    float4 o;
    {
        float top, bot;
        top = v00.x * gx + v01.x * fx;
        bot = v10.x * gx + v11.x * fx;
        o.x = top * gy + bot * fy;
        top = v00.y * gx + v01.y * fx;
        bot = v10.y * gx + v11.y * fx;
        o.y = top * gy + bot * fy;
        top = v00.z * gx + v01.z * fx;
        bot = v10.z * gx + v11.z * fx;
        o.z = top * gy + bot * fy;
        top = v00.w * gx + v01.w * fx;
        bot = v10.w * gx + v11.w * fx;
        o.w = top * gy + bot * fy;
    }

    // Streaming store: evict-first in L2, keep feat resident.
    float4* outp = (float4*)(out + (((size_t)roi * CELLS) + cell) * FC);
    __stcs(outp + c4, o);
}

extern "C" void kernel_launch(void* const* d_in, const int* in_sizes, int n_in,
                              void* d_out, int out_size) {
    const float* feat = (const float*)d_in[0];
    const int*   rois = (const int*)d_in[1];
    float*       out  = (float*)d_out;

    dim3 grid(GROUPS, NUM_ROIS);   // 4 row-consecutive cells per CTA
    roi_pool_kernel<<<grid, 512>>>(feat, rois, out);
}